// round 6
// baseline (speedup 1.0000x reference)
#include <cuda_runtime.h>

// Problem constants (fixed by the reference).
#define BB 320          // batch
#define CC 80           // label dim
#define DD 128          // feature dim
#define NA 30           // num anchors == num blocks
#define NT 320          // threads per block (10 warps); NT == BB

// Cross-block combine scratch (no allocations allowed).
__device__ float g_bsum[NA];
__device__ int   g_bcnt[NA];
__device__ unsigned g_done = 0;   // ticket; last block resets -> replay safe

__device__ __forceinline__ float dot4(float4 a, float4 b) {
    return a.x * b.x + a.y * b.y + a.z * b.z + a.w * b.w;
}

__global__ void __launch_bounds__(NT)
triplet_one(const int* __restrict__ label,
            const float* __restrict__ src,
            const float* __restrict__ tgt,
            float* __restrict__ out) {
    const int t = threadIdx.x;
    const int w = t >> 5;         // 0..9
    const int lane = t & 31;
    const int b = blockIdx.x;     // 0..NA-1: this block owns the rank-b anchor

    __shared__ __align__(16) float s_u10[10][DD];  // per-warp u partials
    __shared__ __align__(16) float s_u[DD];        // u = sum_c t_c / ||t_c||
    __shared__ __align__(16) float s_srcA[DD];     // anchor source row
    __shared__ float s_nt[BB];                     // ||t_c||
    __shared__ float s_ns[BB];                     // ||s_j||
    __shared__ float s_div[BB];                    // diversity per row
    __shared__ float s_sn[BB];                     // sqrt(label popcount)
    __shared__ unsigned s_lp[BB][3];               // packed labels
    __shared__ float s_fd[BB];                     // fd[a, c]
    __shared__ unsigned char s_mask[BB];           // 1 = pos, 2 = neg
    __shared__ float s_posfd[BB];                  // compacted positive fds
    __shared__ float s_rf[10];
    __shared__ int s_ri[10];
    __shared__ int s_npos;
    __shared__ int s_anchor;
    __shared__ int s_last;

    const float4* tgt4 = reinterpret_cast<const float4*>(tgt);
    const float4* src4 = reinterpret_cast<const float4*>(src);

    // ===== Phase 0: pack binary labels (warp per row; no dependencies) =====
    // Hoisted first so these loads overlap phase A's latency.
    {
        const int r0 = w * 32;
#pragma unroll 4
        for (int i = 0; i < 32; i++) {
            const int r = r0 + i;
            unsigned b0 = __ballot_sync(~0u, label[r * CC + lane] != 0);
            unsigned b1 = __ballot_sync(~0u, label[r * CC + 32 + lane] != 0);
            bool pv = (lane < 16) ? (label[r * CC + 64 + lane] != 0) : false;
            unsigned b2 = __ballot_sync(~0u, pv);
            if (lane == 0) {
                s_lp[r][0] = b0; s_lp[r][1] = b1; s_lp[r][2] = b2;
                s_sn[r] = sqrtf((float)(__popc(b0) + __popc(b1) + __popc(b2)));
            }
        }
    }

    // ===== Phase A: target norms + u (warp per column, 32 cols/warp) =======
    // unroll 8: front-batch LDGs -> MLP_eff ~8 against cold DRAM (577/MLP model)
    {
        float ux = 0.f, uy = 0.f, uz = 0.f, uw = 0.f;
        const int c0 = w * 32;
#pragma unroll 8
        for (int i = 0; i < 32; i++) {
            const int c = c0 + i;
            float4 v = tgt4[c * (DD / 4) + lane];       // coalesced 512B/warp
            float sq = dot4(v, v);
#pragma unroll
            for (int o = 16; o > 0; o >>= 1) sq += __shfl_xor_sync(~0u, sq, o);
            float nt_ = sqrtf(sq);
            if (lane == 0) s_nt[c] = nt_;
            float inv = 1.0f / nt_;
            ux += v.x * inv; uy += v.y * inv; uz += v.z * inv; uw += v.w * inv;
        }
        reinterpret_cast<float4*>(s_u10[w])[lane] = make_float4(ux, uy, uz, uw);
    }
    __syncthreads();
    if (t < DD) {
        float s = 0.f;
#pragma unroll
        for (int ww = 0; ww < 10; ww++) s += s_u10[ww][t];   // fixed order
        s_u[t] = s;
    }
    __syncthreads();

    // ===== Phase B: source norms + diversity (warp per row) ================
    // div[j] = 1 - (s_j . u) / (||s_j|| * 320)
    // Exact: clip in fd never binds (Cauchy-Schwarz => sim <= 1), and the
    // eps-max in the denominator never binds for Gaussian rows.
    {
        float4 uu = reinterpret_cast<float4*>(s_u)[lane];
        const int r0 = w * 32;
#pragma unroll 8
        for (int i = 0; i < 32; i++) {
            const int r = r0 + i;
            float4 v = src4[r * (DD / 4) + lane];
            float ss = dot4(v, v);
            float du = dot4(v, uu);
#pragma unroll
            for (int o = 16; o > 0; o >>= 1) {
                ss += __shfl_xor_sync(~0u, ss, o);
                du += __shfl_xor_sync(~0u, du, o);
            }
            if (lane == 0) {
                float ns_ = sqrtf(ss);
                s_ns[r] = ns_;
                s_div[r] = 1.0f - du / (ns_ * 320.0f);
            }
        }
    }
    __syncthreads();

    // ===== Phase C: rank (top_k semantics); this block takes rank == b =====
    // Tie-break by lower index -> ranks form a permutation -> unique writer.
    {
        const float da = s_div[t];
        int cgt = 0;
#pragma unroll 8
        for (int k = 0; k < BB; k++) {
            const float dk = s_div[k];                 // smem broadcast
            cgt += (dk > da || (dk == da && k < t)) ? 1 : 0;
        }
        if (cgt == b) s_anchor = t;                    // exactly one writer
    }
    __syncthreads();
    const int a = s_anchor;

    // issue anchor-row load ASAP (latency hides under other warps' work)
    if (w == 0)
        reinterpret_cast<float4*>(s_srcA)[lane] = src4[a * (DD / 4) + lane];
    __syncthreads();

    // ===== Phase D2: fd[a, c] + pos/neg mask (warp per column) =============
    {
        float4 sa = reinterpret_cast<float4*>(s_srcA)[lane];
        const unsigned la0 = s_lp[a][0], la1 = s_lp[a][1], la2 = s_lp[a][2];
        const float sna = s_sn[a], nsa = s_ns[a];
        const int c0 = w * 32;
#pragma unroll 8
        for (int i = 0; i < 32; i++) {
            const int c = c0 + i;
            float4 v = tgt4[c * (DD / 4) + lane];      // L2-hot (phase A read it)
            float d = dot4(v, sa);
#pragma unroll
            for (int o = 16; o > 0; o >>= 1) d += __shfl_xor_sync(~0u, d, o);
            if (lane == 0) {
                float sim = d / fmaxf(nsa * s_nt[c], 1e-8f);
                s_fd[c] = fmaxf(0.f, 1.f - sim);
                int dl = __popc(la0 & s_lp[c][0]) + __popc(la1 & s_lp[c][1]) +
                         __popc(la2 & s_lp[c][2]);
                float ldv = 1.f - fminf(1.f, (float)dl / (sna * s_sn[c]));
                unsigned char m = 0;
                if (ldv >= 0.5f) m = 2;                       // negative
                else if (ldv <= 0.2f && c != a) m = 1;        // positive
                s_mask[c] = m;
            }
        }
    }
    __syncthreads();

    // ===== Phase D3: deterministic positive compaction (warp 0) ============
    // pos/neg disjoint (gamma < beta) => p != n and a != n are automatic.
    if (w == 0) {
        int np = 0;
#pragma unroll
        for (int j0 = 0; j0 < BB; j0 += 32) {
            bool p = (s_mask[j0 + lane] == 1);
            unsigned bal = __ballot_sync(~0u, p);
            if (p) s_posfd[np + __popc(bal & ((1u << lane) - 1u))] = s_fd[j0 + lane];
            np += __popc(bal);
        }
        if (lane == 0) s_npos = np;
    }
    __syncthreads();
    const int np = s_npos;

    // ===== Phase D4: pair sum (thread t owns column t) =====================
    float lsum = 0.f;
    int lnn = 0;
    if (s_mask[t] == 2) {
        lnn = 1;
        const float fn = s_fd[t];
        for (int p = 0; p < np; p++)
            lsum += fmaxf(0.f, (s_posfd[p] - fn) + 0.5f);
    }
#pragma unroll
    for (int o = 16; o > 0; o >>= 1) {
        lsum += __shfl_xor_sync(~0u, lsum, o);
        lnn += __shfl_xor_sync(~0u, lnn, o);
    }
    if (lane == 0) { s_rf[w] = lsum; s_ri[w] = lnn; }
    __syncthreads();

    // ===== finalize: last-block ticket, fixed-order 30-way combine =========
    if (t == 0) {
        float ts = 0.f; int tn = 0;
#pragma unroll
        for (int ww = 0; ww < 10; ww++) { ts += s_rf[ww]; tn += s_ri[ww]; }
        g_bsum[b] = ts;
        g_bcnt[b] = np * tn;
        __threadfence();
        unsigned tk = atomicAdd(&g_done, 1u);
        s_last = (tk == (unsigned)(NA - 1)) ? 1 : 0;
    }
    __syncthreads();

    if (s_last) {
        if (t == 0) g_done = 0;          // reset for next graph replay
        __threadfence();                 // acquire other blocks' partials
        if (w == 0) {
            float ps = (lane < NA) ? g_bsum[lane] : 0.f;
            int pc = (lane < NA) ? g_bcnt[lane] : 0;
#pragma unroll
            for (int o = 16; o > 0; o >>= 1) {
                ps += __shfl_xor_sync(~0u, ps, o);
                pc += __shfl_xor_sync(~0u, pc, o);
            }
            if (lane == 0) out[0] = ps / ((float)pc + 1e-4f);
        }
    }
}

extern "C" void kernel_launch(void* const* d_in, const int* in_sizes, int n_in,
                              void* d_out, int out_size) {
    const int* label = (const int*)d_in[0];
    const float* src = (const float*)d_in[1];
    const float* tgt = (const float*)d_in[2];
    float* out = (float*)d_out;
    (void)in_sizes; (void)n_in; (void)out_size;

    triplet_one<<<NA, NT>>>(label, src, tgt, out);
}

// round 11
// speedup vs baseline: 1.6169x; 1.6169x over previous
#include <cuda_runtime.h>

// Problem constants (fixed by the reference).
#define BB 320          // batch
#define CC 80           // label dim
#define DD 128          // feature dim
#define NA 30           // num anchors == num blocks
#define NT 320          // threads per block (10 warps); NT == BB
#define WREG 576        // floats of staging per warp (2304 B, 16B-aligned)

// Cross-block combine scratch (no allocations allowed).
__device__ float g_bsum[NA];
__device__ int   g_bcnt[NA];
__device__ unsigned g_done = 0;   // ticket; last block resets -> replay safe

__device__ __forceinline__ float dot4(float4 a, float4 b) {
    return a.x * b.x + a.y * b.y + a.z * b.z + a.w * b.w;
}

extern __shared__ __align__(16) float dyn[];   // 10 * WREG floats

__global__ void __launch_bounds__(NT)
triplet_v3(const int* __restrict__ label,
           const float* __restrict__ src,
           const float* __restrict__ tgt,
           float* __restrict__ out) {
    const int t = threadIdx.x;
    const int w = t >> 5;         // 0..9
    const int lane = t & 31;
    const int b = blockIdx.x;     // this block owns the rank-b anchor

    __shared__ __align__(16) float s_u[DD];      // u = sum_c t_c / ||t_c||
    __shared__ __align__(16) float s_srcA[DD];   // anchor source row
    __shared__ __align__(16) float s_div[BB];    // diversity per row
    __shared__ float s_nt[BB];                   // ||t_c||
    __shared__ float s_ns[BB];                   // ||s_j||
    __shared__ float s_sn[BB];                   // sqrt(label popcount)
    __shared__ unsigned s_lp[BB][3];             // packed labels
    __shared__ float s_fd[BB];                   // fd[a, c]
    __shared__ unsigned char s_mask[BB];         // 1 = pos, 2 = neg
    __shared__ float s_posfd[BB];                // compacted positive fds
    __shared__ float s_rf[10];
    __shared__ int s_ri[10];
    __shared__ int s_npos;
    __shared__ int s_anchor;
    __shared__ int s_last;

    float* preg = dyn + w * WREG;                // this warp's staging tile

    const float4* tgt4 = reinterpret_cast<const float4*>(tgt);
    const float4* src4 = reinterpret_cast<const float4*>(src);

    // ===== Phase 0: pack binary labels (warp per 32 rows; independent) =====
    {
        const int r0 = w * 32;
#pragma unroll 4
        for (int i = 0; i < 32; i++) {
            const int r = r0 + i;
            unsigned b0 = __ballot_sync(~0u, label[r * CC + lane] != 0);
            unsigned b1 = __ballot_sync(~0u, label[r * CC + 32 + lane] != 0);
            bool pv = (lane < 16) ? (label[r * CC + 64 + lane] != 0) : false;
            unsigned b2 = __ballot_sync(~0u, pv);
            if (lane == 0) {
                s_lp[r][0] = b0; s_lp[r][1] = b1; s_lp[r][2] = b2;
                s_sn[r] = sqrtf((float)(__popc(b0) + __popc(b1) + __popc(b2)));
            }
        }
    }

    // ===== Phase A: target norms via transpose reduction (no shfl trees) ===
    // 2 sub-passes of 16 columns; staging stride 34 -> (near) conflict-free.
    {
        const int c0 = w * 32;
#pragma unroll
        for (int h = 0; h < 2; h++) {
#pragma unroll 8
            for (int i = 0; i < 16; i++) {        // independent LDG+STS: full MLP
                float4 v = tgt4[(c0 + h * 16 + i) * (DD / 4) + lane];
                preg[i * 34 + lane] = dot4(v, v);
            }
            __syncwarp();
            {
                const int row = lane & 15;
                const int off = (lane >> 4) * 16;
                const float* pr = preg + row * 34 + off;
                float s0 = 0.f, s1 = 0.f;
#pragma unroll
                for (int l = 0; l < 16; l += 2) { s0 += pr[l]; s1 += pr[l + 1]; }
                float s = s0 + s1;
                s += __shfl_xor_sync(~0u, s, 16);
                if (lane < 16) s_nt[c0 + h * 16 + row] = sqrtf(s);
            }
            __syncwarp();
        }
        // u accumulation: re-read (L1/L2-hot), no reduction needed at all.
        float ux = 0.f, uy = 0.f, uz = 0.f, uw = 0.f;
#pragma unroll 8
        for (int i = 0; i < 32; i++) {
            float4 v = tgt4[(c0 + i) * (DD / 4) + lane];
            float inv = 1.0f / s_nt[c0 + i];
            ux += v.x * inv; uy += v.y * inv; uz += v.z * inv; uw += v.w * inv;
        }
        __syncwarp();
        reinterpret_cast<float4*>(preg)[lane] = make_float4(ux, uy, uz, uw);
    }
    __syncthreads();
    if (t < DD) {                                  // fixed-order 10-way combine
        float s = 0.f;
#pragma unroll
        for (int ww = 0; ww < 10; ww++) s += dyn[ww * WREG + t];
        s_u[t] = s;
    }
    __syncthreads();

    // ===== Phase B: source norms + diversity (transpose reduction) =========
    // div[j] = 1 - (s_j . u) / (||s_j|| * 320)   [validated exact in R6]
    // 4 sub-passes of 8 rows; ss at stride-35 rows, du at +280.
    {
        const int r0 = w * 32;
        const float4 uu = reinterpret_cast<const float4*>(s_u)[lane];
#pragma unroll
        for (int h = 0; h < 4; h++) {
#pragma unroll 8
            for (int i = 0; i < 8; i++) {
                float4 v = src4[(r0 + h * 8 + i) * (DD / 4) + lane];
                preg[i * 35 + lane] = dot4(v, v);
                preg[280 + i * 35 + lane] = dot4(v, uu);
            }
            __syncwarp();
            {
                const int row = lane & 7;
                const int off = (lane >> 3) * 8;
                const float* ps = preg + row * 35 + off;
                const float* pd = ps + 280;
                float ss = 0.f, du = 0.f;
#pragma unroll
                for (int l = 0; l < 8; l++) { ss += ps[l]; du += pd[l]; }
                ss += __shfl_xor_sync(~0u, ss, 8);
                du += __shfl_xor_sync(~0u, du, 8);
                ss += __shfl_xor_sync(~0u, ss, 16);
                du += __shfl_xor_sync(~0u, du, 16);
                if (lane < 8) {
                    const int r = r0 + h * 8 + row;
                    float ns_ = sqrtf(ss);
                    s_ns[r] = ns_;
                    s_div[r] = 1.0f - du / (ns_ * 320.0f);
                }
            }
            __syncwarp();
        }
    }
    __syncthreads();

    // ===== Phase C: rank (top_k tie-break -> permutation); take rank == b ==
    {
        const float da = s_div[t];
        const float4* dv4 = reinterpret_cast<const float4*>(s_div);
        int cgt = 0;
#pragma unroll 4
        for (int k4 = 0; k4 < BB / 4; k4++) {
            float4 d4 = dv4[k4];
            const int k = k4 * 4;
            cgt += (d4.x > da || (d4.x == da && (k + 0) < t)) ? 1 : 0;
            cgt += (d4.y > da || (d4.y == da && (k + 1) < t)) ? 1 : 0;
            cgt += (d4.z > da || (d4.z == da && (k + 2) < t)) ? 1 : 0;
            cgt += (d4.w > da || (d4.w == da && (k + 3) < t)) ? 1 : 0;
        }
        if (cgt == b) s_anchor = t;               // exactly one writer
    }
    __syncthreads();
    const int a = s_anchor;

    if (w == 0)
        reinterpret_cast<float4*>(s_srcA)[lane] = src4[a * (DD / 4) + lane];
    __syncthreads();

    // ===== Phase D: fd[a,c] + pos/neg mask (transpose reduction, all lanes)
    {
        const int c0 = w * 32;
        const float4 sa = reinterpret_cast<const float4*>(s_srcA)[lane];
        const unsigned la0 = s_lp[a][0], la1 = s_lp[a][1], la2 = s_lp[a][2];
        const float sna = s_sn[a], nsa = s_ns[a];
#pragma unroll
        for (int h = 0; h < 2; h++) {
#pragma unroll 8
            for (int i = 0; i < 16; i++) {
                float4 v = tgt4[(c0 + h * 16 + i) * (DD / 4) + lane];
                preg[i * 34 + lane] = dot4(v, sa);
            }
            __syncwarp();
            {
                const int row = lane & 15;
                const int off = (lane >> 4) * 16;
                const float* pr = preg + row * 34 + off;
                float s0 = 0.f, s1 = 0.f;
#pragma unroll
                for (int l = 0; l < 16; l += 2) { s0 += pr[l]; s1 += pr[l + 1]; }
                float d = s0 + s1;
                d += __shfl_xor_sync(~0u, d, 16);
                if (lane < 16) {
                    const int c = c0 + h * 16 + row;
                    float sim = d / fmaxf(nsa * s_nt[c], 1e-8f);
                    s_fd[c] = fmaxf(0.f, 1.f - sim);
                    int dl = __popc(la0 & s_lp[c][0]) + __popc(la1 & s_lp[c][1]) +
                             __popc(la2 & s_lp[c][2]);
                    float ldv = 1.f - fminf(1.f, (float)dl / (sna * s_sn[c]));
                    unsigned char m = 0;
                    if (ldv >= 0.5f) m = 2;                    // negative
                    else if (ldv <= 0.2f && c != a) m = 1;     // positive
                    s_mask[c] = m;
                }
            }
            __syncwarp();
        }
    }
    __syncthreads();

    // ===== Phase D3: deterministic positive compaction (warp 0) ============
    // pos/neg disjoint (gamma < beta) => p != n and a != n are automatic.
    int np;
    if (w == 0) {
        int acc = 0;
#pragma unroll
        for (int j0 = 0; j0 < BB; j0 += 32) {
            bool p = (s_mask[j0 + lane] == 1);
            unsigned bal = __ballot_sync(~0u, p);
            if (p) s_posfd[acc + __popc(bal & ((1u << lane) - 1u))] = s_fd[j0 + lane];
            acc += __popc(bal);
        }
        if (lane == 0) s_npos = acc;
    }
    __syncthreads();
    np = s_npos;

    // ===== Phase D4: pair sum (thread t owns column t) =====================
    float lsum = 0.f;
    int lnn = 0;
    if (s_mask[t] == 2) {
        lnn = 1;
        const float fn = s_fd[t];
        for (int p = 0; p < np; p++)
            lsum += fmaxf(0.f, (s_posfd[p] - fn) + 0.5f);
    }
#pragma unroll
    for (int o = 16; o > 0; o >>= 1) {
        lsum += __shfl_xor_sync(~0u, lsum, o);
        lnn += __shfl_xor_sync(~0u, lnn, o);
    }
    if (lane == 0) { s_rf[w] = lsum; s_ri[w] = lnn; }
    __syncthreads();

    // ===== finalize: last-block ticket, fixed-order 30-way combine =========
    if (t == 0) {
        float ts = 0.f; int tn = 0;
#pragma unroll
        for (int ww = 0; ww < 10; ww++) { ts += s_rf[ww]; tn += s_ri[ww]; }
        g_bsum[b] = ts;
        g_bcnt[b] = np * tn;
        __threadfence();
        unsigned tk = atomicAdd(&g_done, 1u);
        s_last = (tk == (unsigned)(NA - 1)) ? 1 : 0;
    }
    __syncthreads();

    if (s_last) {
        if (t == 0) g_done = 0;          // reset for next graph replay
        __threadfence();                 // acquire other blocks' partials
        if (w == 0) {
            float ps = (lane < NA) ? g_bsum[lane] : 0.f;
            int pc = (lane < NA) ? g_bcnt[lane] : 0;
#pragma unroll
            for (int o = 16; o > 0; o >>= 1) {
                ps += __shfl_xor_sync(~0u, ps, o);
                pc += __shfl_xor_sync(~0u, pc, o);
            }
            if (lane == 0) out[0] = ps / ((float)pc + 1e-4f);
        }
    }
}

extern "C" void kernel_launch(void* const* d_in, const int* in_sizes, int n_in,
                              void* d_out, int out_size) {
    const int* label = (const int*)d_in[0];
    const float* src = (const float*)d_in[1];
    const float* tgt = (const float*)d_in[2];
    float* out = (float*)d_out;
    (void)in_sizes; (void)n_in; (void)out_size;

    triplet_v3<<<NA, NT, 10 * WREG * (int)sizeof(float)>>>(label, src, tgt, out);
}